// round 1
// baseline (speedup 1.0000x reference)
#include <cuda_runtime.h>
#include <cfloat>
#include <math.h>

#define BB 8
#define NN 1024
#define DD 2048

// Scratch (allocation-free rule: static __device__ arrays)
static __device__ float g_K[BB * NN * DD];
static __device__ float g_Q[BB * NN * DD];
static __device__ float g_V[BB * NN * DD];
static __device__ float g_mid[BB * NN * DD];

// ---------------------------------------------------------------------------
// C[M,Nc] = alpha * A[M,K] * B[Nc,K]^T      (all row-major, batched via z)
// Tiles: 128x128x16, 256 threads, 8x8 per thread.
// ---------------------------------------------------------------------------
__global__ __launch_bounds__(256) void gemm_nt_k(
    const float* __restrict__ A, const float* __restrict__ Bm, float* __restrict__ C,
    int M, int Nc, int K, long sA, long sB, long sC, float alpha)
{
    __shared__ float As[16][128];
    __shared__ float Bs[16][128];

    const float* Ab = A + (long)blockIdx.z * sA;
    const float* Bb = Bm + (long)blockIdx.z * sB;
    float* Cb = C + (long)blockIdx.z * sC;

    const int m0 = blockIdx.y * 128;
    const int n0 = blockIdx.x * 128;
    const int tid = threadIdx.x;
    const int ty = tid >> 4;          // 0..15
    const int tx = tid & 15;          // 0..15
    const int lrow = tid >> 2;        // 0..63
    const int lcol = (tid & 3) << 2;  // 0,4,8,12

    float acc[8][8];
#pragma unroll
    for (int i = 0; i < 8; i++)
#pragma unroll
        for (int j = 0; j < 8; j++) acc[i][j] = 0.f;

    for (int k0 = 0; k0 < K; k0 += 16) {
#pragma unroll
        for (int r = 0; r < 2; r++) {
            int mr = lrow + r * 64;
            float4 va = *reinterpret_cast<const float4*>(Ab + (long)(m0 + mr) * K + k0 + lcol);
            As[lcol + 0][mr] = va.x; As[lcol + 1][mr] = va.y;
            As[lcol + 2][mr] = va.z; As[lcol + 3][mr] = va.w;
            float4 vb = *reinterpret_cast<const float4*>(Bb + (long)(n0 + mr) * K + k0 + lcol);
            Bs[lcol + 0][mr] = vb.x; Bs[lcol + 1][mr] = vb.y;
            Bs[lcol + 2][mr] = vb.z; Bs[lcol + 3][mr] = vb.w;
        }
        __syncthreads();
#pragma unroll
        for (int kk = 0; kk < 16; kk++) {
            float a[8], b[8];
#pragma unroll
            for (int i = 0; i < 8; i++) a[i] = As[kk][ty * 8 + i];
#pragma unroll
            for (int j = 0; j < 8; j++) b[j] = Bs[kk][tx * 8 + j];
#pragma unroll
            for (int i = 0; i < 8; i++)
#pragma unroll
                for (int j = 0; j < 8; j++) acc[i][j] += a[i] * b[j];
        }
        __syncthreads();
    }

#pragma unroll
    for (int i = 0; i < 8; i++) {
        int m = m0 + ty * 8 + i;
#pragma unroll
        for (int j = 0; j < 8; j += 4) {
            float4 v = make_float4(alpha * acc[i][j + 0], alpha * acc[i][j + 1],
                                   alpha * acc[i][j + 2], alpha * acc[i][j + 3]);
            *reinterpret_cast<float4*>(Cb + (long)m * Nc + n0 + tx * 8 + j) = v;
        }
    }
}

// ---------------------------------------------------------------------------
// C[M,Nc] = A^T * B   where A is [K,M] row-major, B is [K,Nc] row-major.
// (attention apply: out_mid[i,d] = sum_j Aw[j,i] * V[j,d])
// ---------------------------------------------------------------------------
__global__ __launch_bounds__(256) void gemm_tn_k(
    const float* __restrict__ A, const float* __restrict__ Bm, float* __restrict__ C,
    int M, int Nc, int K, long sA, long sB, long sC)
{
    __shared__ float As[16][128];
    __shared__ float Bs[16][128];

    const float* Ab = A + (long)blockIdx.z * sA;
    const float* Bb = Bm + (long)blockIdx.z * sB;
    float* Cb = C + (long)blockIdx.z * sC;

    const int m0 = blockIdx.y * 128;
    const int n0 = blockIdx.x * 128;
    const int tid = threadIdx.x;
    const int ty = tid >> 4;
    const int tx = tid & 15;
    const int lrow = tid >> 5;         // 0..7
    const int lcol = (tid & 31) << 2;  // 0..124

    float acc[8][8];
#pragma unroll
    for (int i = 0; i < 8; i++)
#pragma unroll
        for (int j = 0; j < 8; j++) acc[i][j] = 0.f;

    for (int k0 = 0; k0 < K; k0 += 16) {
#pragma unroll
        for (int r = 0; r < 2; r++) {
            int kr = lrow + r * 8;
            float4 va = *reinterpret_cast<const float4*>(Ab + (long)(k0 + kr) * M + m0 + lcol);
            *reinterpret_cast<float4*>(&As[kr][lcol]) = va;
            float4 vb = *reinterpret_cast<const float4*>(Bb + (long)(k0 + kr) * Nc + n0 + lcol);
            *reinterpret_cast<float4*>(&Bs[kr][lcol]) = vb;
        }
        __syncthreads();
#pragma unroll
        for (int kk = 0; kk < 16; kk++) {
            float a[8], b[8];
#pragma unroll
            for (int i = 0; i < 8; i++) a[i] = As[kk][ty * 8 + i];
#pragma unroll
            for (int j = 0; j < 8; j++) b[j] = Bs[kk][tx * 8 + j];
#pragma unroll
            for (int i = 0; i < 8; i++)
#pragma unroll
                for (int j = 0; j < 8; j++) acc[i][j] += a[i] * b[j];
        }
        __syncthreads();
    }

#pragma unroll
    for (int i = 0; i < 8; i++) {
        int m = m0 + ty * 8 + i;
#pragma unroll
        for (int j = 0; j < 8; j += 4) {
            float4 v = make_float4(acc[i][j + 0], acc[i][j + 1], acc[i][j + 2], acc[i][j + 3]);
            *reinterpret_cast<float4*>(Cb + (long)m * Nc + n0 + tx * 8 + j) = v;
        }
    }
}

// ---------------------------------------------------------------------------
// Softmax over axis=1 (normalize each COLUMN j over rows i), diagonal excluded
// (reference masks logits[j][j] = -inf  =>  weight exactly 0). In-place.
// One thread per column; reads are coalesced (consecutive j across threads).
// ---------------------------------------------------------------------------
__global__ __launch_bounds__(256) void softmax_dim1_k(float* __restrict__ Aw)
{
    const int j = blockIdx.x * blockDim.x + threadIdx.x;
    float* Mb = Aw + (long)blockIdx.y * NN * NN;

    float mx = -FLT_MAX;
    for (int i = 0; i < NN; i++) {
        float v = Mb[(long)i * NN + j];
        if (i != j) mx = fmaxf(mx, v);
    }
    float s = 0.f;
    for (int i = 0; i < NN; i++) {
        float v = Mb[(long)i * NN + j];
        float e = (i == j) ? 0.f : __expf(v - mx);
        s += e;
        Mb[(long)i * NN + j] = e;
    }
    float inv = 1.f / s;
    for (int i = 0; i < NN; i++) {
        Mb[(long)i * NN + j] *= inv;
    }
}

// ---------------------------------------------------------------------------
extern "C" void kernel_launch(void* const* d_in, const int* in_sizes, int n_in,
                              void* d_out, int out_size)
{
    const float* y  = (const float*)d_in[0];
    const float* Wk = (const float*)d_in[1];
    const float* Wq = (const float*)d_in[2];
    const float* Wv = (const float*)d_in[3];
    const float* Wo = (const float*)d_in[4];

    float* out = (float*)d_out;                       // [B,N,D]
    float* Aw  = out + (long)BB * NN * DD;            // [B,N,N] attention weights

    float *gK, *gQ, *gV, *gMid;
    cudaGetSymbolAddress((void**)&gK,   g_K);
    cudaGetSymbolAddress((void**)&gQ,   g_Q);
    cudaGetSymbolAddress((void**)&gV,   g_V);
    cudaGetSymbolAddress((void**)&gMid, g_mid);

    const long nd = (long)NN * DD;   // per-batch K/Q/V stride
    const long nn = (long)NN * NN;   // per-batch attention stride

    // 1) Projections over flattened rows (B*N = 8192):  X = y @ W^T
    {
        dim3 grid(DD / 128, (BB * NN) / 128, 1);
        gemm_nt_k<<<grid, 256>>>(y, Wk, gK, BB * NN, DD, DD, 0, 0, 0, 1.0f);
        gemm_nt_k<<<grid, 256>>>(y, Wq, gQ, BB * NN, DD, DD, 0, 0, 0, 0.1f);
        gemm_nt_k<<<grid, 256>>>(y, Wv, gV, BB * NN, DD, DD, 0, 0, 0, 1.0f);
    }

    // 2) Logits per batch: S_b = Q_b @ K_b^T  -> written straight into Aw
    {
        dim3 grid(NN / 128, NN / 128, BB);
        gemm_nt_k<<<grid, 256>>>(gQ, gK, Aw, NN, NN, DD, nd, nd, nn, 1.0f);
    }

    // 3) Column-wise softmax (axis=1) with diagonal exclusion, in-place
    {
        dim3 grid(NN / 256, BB, 1);
        softmax_dim1_k<<<grid, 256>>>(Aw);
    }

    // 4) mid_b = Aw_b^T @ V_b   (out[b,i,:] = sum_j Aw[b,j,i] * V[b,j,:])
    {
        dim3 grid(DD / 128, NN / 128, BB);
        gemm_tn_k<<<grid, 256>>>(Aw, gV, gMid, NN, DD, NN, nn, nd, nd);
    }

    // 5) out = mid @ Wo^T over flattened rows
    {
        dim3 grid(DD / 128, (BB * NN) / 128, 1);
        gemm_nt_k<<<grid, 256>>>(gMid, Wo, out, BB * NN, DD, DD, 0, 0, 0, 1.0f);
    }
}

// round 3
// speedup vs baseline: 2.6692x; 2.6692x over previous
#include <cuda_runtime.h>
#include <cuda_bf16.h>
#include <cstdint>
#include <cfloat>
#include <math.h>

#define BB 8
#define NN 1024
#define DD 2048

// ---------------------------------------------------------------------------
// Scratch (allocation-free rule: static __device__ arrays)
// ---------------------------------------------------------------------------
static __device__ __align__(16) __nv_bfloat16 g_yh[BB * NN * DD], g_yl[BB * NN * DD];
static __device__ __align__(16) __nv_bfloat16 g_Wh[4 * DD * DD], g_Wl[4 * DD * DD]; // k,q,v,o
static __device__ __align__(16) __nv_bfloat16 g_Kh[BB * NN * DD], g_Kl[BB * NN * DD];
static __device__ __align__(16) __nv_bfloat16 g_Qh[BB * NN * DD], g_Ql[BB * NN * DD];
static __device__ __align__(16) float         g_V [BB * NN * DD];
static __device__ __align__(16) __nv_bfloat16 g_VTh[BB * NN * DD], g_VTl[BB * NN * DD];
static __device__ __align__(16) __nv_bfloat16 g_ATh[BB * NN * NN], g_ATl[BB * NN * NN];
static __device__ __align__(16) __nv_bfloat16 g_mh[BB * NN * DD], g_ml[BB * NN * DD];

// ---------------------------------------------------------------------------
// Baseline-PTX helpers (sm_103 non-'a' target: mma.sync / ldmatrix / cp.async)
// ---------------------------------------------------------------------------
__device__ __forceinline__ uint32_t smem_u32(const void* p) {
    uint32_t a;
    asm("{ .reg .u64 t; cvta.to.shared.u64 t, %1; cvt.u32.u64 %0, t; }" : "=r"(a) : "l"(p));
    return a;
}

__device__ __forceinline__ void cp16(uint32_t dst, const void* src) {
    asm volatile("cp.async.cg.shared.global [%0], [%1], 16;" :: "r"(dst), "l"(src) : "memory");
}
#define CP_COMMIT() asm volatile("cp.async.commit_group;" ::: "memory")
#define CP_WAIT1()  asm volatile("cp.async.wait_group 1;" ::: "memory")

__device__ __forceinline__ void ldm_x4(uint32_t& r0, uint32_t& r1, uint32_t& r2, uint32_t& r3,
                                       uint32_t addr) {
    asm volatile("ldmatrix.sync.aligned.m8n8.x4.shared.b16 {%0,%1,%2,%3}, [%4];"
                 : "=r"(r0), "=r"(r1), "=r"(r2), "=r"(r3) : "r"(addr));
}

__device__ __forceinline__ void mma_bf16(float* c, const uint32_t* a, const uint32_t* b) {
    asm volatile(
        "mma.sync.aligned.m16n8k16.row.col.f32.bf16.bf16.f32 "
        "{%0,%1,%2,%3}, {%4,%5,%6,%7}, {%8,%9}, {%0,%1,%2,%3};"
        : "+f"(c[0]), "+f"(c[1]), "+f"(c[2]), "+f"(c[3])
        : "r"(a[0]), "r"(a[1]), "r"(a[2]), "r"(a[3]), "r"(b[0]), "r"(b[1]));
}

// ---------------------------------------------------------------------------
// HMMA GEMM:  C[M,Nc] = alpha * A[M,K] * B[Nc,K]^T   (bf16 hi/lo, fp32 acc)
// tile 128x128x32, 256 threads (8 warps, each 64x32), cp.async double buffer.
// SMEM rows padded to 80B (conflict-free ldmatrix phases).
// mode 0: fp32 C.   mode 1: bf16 hi/lo split C.
// ---------------------------------------------------------------------------
#define ROWB   80                 // bytes per 32-element bf16 row (64B data + 16B pad)
#define MATB   (128 * ROWB)       // 10240 B per matrix tile
#define STAGEB (4 * MATB)         // Ah, Al, Bh, Bl
#define SMEMB  (2 * STAGEB)       // 81920 B

__global__ __launch_bounds__(256, 1) void gemm_hmma(
    const __nv_bfloat16* __restrict__ Ah, const __nv_bfloat16* __restrict__ Al,
    const __nv_bfloat16* __restrict__ Bh, const __nv_bfloat16* __restrict__ Bl,
    float* __restrict__ Cf, __nv_bfloat16* __restrict__ Ch, __nv_bfloat16* __restrict__ Cl,
    int Nc, int K, long sA, long sB, long sC, float alpha, int mode)
{
    extern __shared__ char smem[];
    const uint32_t sb = smem_u32(smem);

    const int tid  = threadIdx.x;
    const int wid  = tid >> 5;
    const int lane = tid & 31;
    const int m0 = blockIdx.y * 128, n0 = blockIdx.x * 128;

    const __nv_bfloat16* pA[2] = { Ah + (long)blockIdx.z * sA + (long)m0 * K,
                                   Al + (long)blockIdx.z * sA + (long)m0 * K };
    const __nv_bfloat16* pB[2] = { Bh + (long)blockIdx.z * sB + (long)n0 * K,
                                   Bl + (long)blockIdx.z * sB + (long)n0 * K };
    const long zC = (long)blockIdx.z * sC;

    // copy indices: 2 x 16B per matrix per thread (128 rows x 4 chunks = 512)
    const int u0 = tid, u1 = tid + 256;
    const int r0c = u0 >> 2, q0 = u0 & 3;
    const int r1c = u1 >> 2, q1 = u1 & 3;

    const int wm0 = (wid >> 2) * 64;   // warp row offset in tile
    const int wn0 = (wid & 3) * 32;    // warp col offset in tile

    // ldmatrix lane addressing
    const int a_row  = lane & 15;            // + 16*mi + wm0
    const int a_koff = (lane >> 4) * 16;     // byte offset within slab
    const int b_row  = ((lane >> 3) & 2) * 4 + (lane & 7);  // + 8? covers 16 n-rows
    const int b_koff = ((lane >> 3) & 1) * 16;

    float acc[4][4][4];
#pragma unroll
    for (int i = 0; i < 4; i++)
#pragma unroll
        for (int j = 0; j < 4; j++)
#pragma unroll
            for (int k = 0; k < 4; k++) acc[i][j][k] = 0.f;

    const int nst = K >> 5;   // K/32 stages

    // ---- issue stage 0 ----
    {
        const int k0 = 0;
        uint32_t s0 = sb;
#pragma unroll
        for (int m = 0; m < 2; m++) {
            cp16(s0 + m * MATB + r0c * ROWB + q0 * 16, pA[m] + (long)r0c * K + k0 + q0 * 8);
            cp16(s0 + m * MATB + r1c * ROWB + q1 * 16, pA[m] + (long)r1c * K + k0 + q1 * 8);
            cp16(s0 + (2 + m) * MATB + r0c * ROWB + q0 * 16, pB[m] + (long)r0c * K + k0 + q0 * 8);
            cp16(s0 + (2 + m) * MATB + r1c * ROWB + q1 * 16, pB[m] + (long)r1c * K + k0 + q1 * 8);
        }
        CP_COMMIT();
    }

    for (int c = 0; c < nst; c++) {
        // ---- prefetch stage c+1 ----
        if (c + 1 < nst) {
            const int k0 = (c + 1) << 5;
            uint32_t s1 = sb + ((c + 1) & 1) * STAGEB;
#pragma unroll
            for (int m = 0; m < 2; m++) {
                cp16(s1 + m * MATB + r0c * ROWB + q0 * 16, pA[m] + (long)r0c * K + k0 + q0 * 8);
                cp16(s1 + m * MATB + r1c * ROWB + q1 * 16, pA[m] + (long)r1c * K + k0 + q1 * 8);
                cp16(s1 + (2 + m) * MATB + r0c * ROWB + q0 * 16, pB[m] + (long)r0c * K + k0 + q0 * 8);
                cp16(s1 + (2 + m) * MATB + r1c * ROWB + q1 * 16, pB[m] + (long)r1c * K + k0 + q1 * 8);
            }
        }
        CP_COMMIT();
        CP_WAIT1();          // stage c resident (next stage may be in flight)
        __syncthreads();

        const uint32_t st = sb + (c & 1) * STAGEB;
        const uint32_t aHb = st + 0 * MATB + (wm0 + a_row) * ROWB + a_koff;
        const uint32_t aLb = st + 1 * MATB + (wm0 + a_row) * ROWB + a_koff;
        const uint32_t bHb = st + 2 * MATB + (wn0 + b_row) * ROWB + b_koff;
        const uint32_t bLb = st + 3 * MATB + (wn0 + b_row) * ROWB + b_koff;

#pragma unroll
        for (int s = 0; s < 2; s++) {      // two k16 slabs in the 32-wide stage
            const int sk = s * 32;         // byte offset of slab
            uint32_t ah[4][4], al[4][4], bh[2][4], bl[2][4];
#pragma unroll
            for (int mi = 0; mi < 4; mi++) {
                ldm_x4(ah[mi][0], ah[mi][1], ah[mi][2], ah[mi][3], aHb + mi * 16 * ROWB + sk);
                ldm_x4(al[mi][0], al[mi][1], al[mi][2], al[mi][3], aLb + mi * 16 * ROWB + sk);
            }
#pragma unroll
            for (int nb = 0; nb < 2; nb++) {
                ldm_x4(bh[nb][0], bh[nb][1], bh[nb][2], bh[nb][3], bHb + nb * 16 * ROWB + sk);
                ldm_x4(bl[nb][0], bl[nb][1], bl[nb][2], bl[nb][3], bLb + nb * 16 * ROWB + sk);
            }
#pragma unroll
            for (int mi = 0; mi < 4; mi++)
#pragma unroll
                for (int ni = 0; ni < 4; ni++) {
                    const uint32_t* bhf = &bh[ni >> 1][(ni & 1) * 2];
                    const uint32_t* blf = &bl[ni >> 1][(ni & 1) * 2];
                    mma_bf16(acc[mi][ni], ah[mi], bhf);
                    mma_bf16(acc[mi][ni], ah[mi], blf);
                    mma_bf16(acc[mi][ni], al[mi], bhf);
                }
        }
        __syncthreads();     // compute done before next issue overwrites buffer
    }

    // ---- epilogue: registers -> GMEM directly ----
    const int er = lane >> 2;          // 0..7
    const int ec = (lane & 3) * 2;     // 0,2,4,6
#pragma unroll
    for (int mi = 0; mi < 4; mi++) {
#pragma unroll
        for (int ni = 0; ni < 4; ni++) {
            const int row = m0 + wm0 + 16 * mi + er;
            const int col = n0 + wn0 + 8 * ni + ec;
            float v0 = acc[mi][ni][0] * alpha, v1 = acc[mi][ni][1] * alpha;
            float v2 = acc[mi][ni][2] * alpha, v3 = acc[mi][ni][3] * alpha;
            if (mode == 0) {
                *reinterpret_cast<float2*>(Cf + zC + (long)row * Nc + col) = make_float2(v0, v1);
                *reinterpret_cast<float2*>(Cf + zC + (long)(row + 8) * Nc + col) = make_float2(v2, v3);
            } else {
                __nv_bfloat162 h, l;
                h.x = __float2bfloat16(v0); l.x = __float2bfloat16(v0 - __bfloat162float(h.x));
                h.y = __float2bfloat16(v1); l.y = __float2bfloat16(v1 - __bfloat162float(h.y));
                *reinterpret_cast<__nv_bfloat162*>(Ch + zC + (long)row * Nc + col) = h;
                *reinterpret_cast<__nv_bfloat162*>(Cl + zC + (long)row * Nc + col) = l;
                h.x = __float2bfloat16(v2); l.x = __float2bfloat16(v2 - __bfloat162float(h.x));
                h.y = __float2bfloat16(v3); l.y = __float2bfloat16(v3 - __bfloat162float(h.y));
                *reinterpret_cast<__nv_bfloat162*>(Ch + zC + (long)(row + 8) * Nc + col) = h;
                *reinterpret_cast<__nv_bfloat162*>(Cl + zC + (long)(row + 8) * Nc + col) = l;
            }
        }
    }
}

// ---------------------------------------------------------------------------
// fp32 -> bf16 hi/lo elementwise split
// ---------------------------------------------------------------------------
__global__ __launch_bounds__(256) void splitf_k(const float* __restrict__ x,
    __nv_bfloat16* __restrict__ hi, __nv_bfloat16* __restrict__ lo, long n)
{
    long i = ((long)blockIdx.x * 256 + threadIdx.x) * 4;
    if (i >= n) return;
    float4 v = *reinterpret_cast<const float4*>(x + i);
    __nv_bfloat162 h01, h23, l01, l23;
    h01.x = __float2bfloat16(v.x); l01.x = __float2bfloat16(v.x - __bfloat162float(h01.x));
    h01.y = __float2bfloat16(v.y); l01.y = __float2bfloat16(v.y - __bfloat162float(h01.y));
    h23.x = __float2bfloat16(v.z); l23.x = __float2bfloat16(v.z - __bfloat162float(h23.x));
    h23.y = __float2bfloat16(v.w); l23.y = __float2bfloat16(v.w - __bfloat162float(h23.y));
    uint2 hv, lv;
    hv.x = *reinterpret_cast<uint32_t*>(&h01); hv.y = *reinterpret_cast<uint32_t*>(&h23);
    lv.x = *reinterpret_cast<uint32_t*>(&l01); lv.y = *reinterpret_cast<uint32_t*>(&l23);
    *reinterpret_cast<uint2*>(hi + i) = hv;
    *reinterpret_cast<uint2*>(lo + i) = lv;
}

// ---------------------------------------------------------------------------
// transpose + split: out[c][r] = split(in[r][c]); in [R,C] fp32, out [C,R] bf16
// ---------------------------------------------------------------------------
__global__ __launch_bounds__(256) void tsplit_k(const float* __restrict__ in,
    __nv_bfloat16* __restrict__ oh, __nv_bfloat16* __restrict__ ol,
    int R, int C, long sIn, long sOut)
{
    __shared__ float t[32][33];
    const float* ib = in + (long)blockIdx.z * sIn;
    int r0 = blockIdx.y * 32, c0 = blockIdx.x * 32;
    int tx = threadIdx.x, ty = threadIdx.y;
#pragma unroll
    for (int i = 0; i < 4; i++)
        t[ty + i * 8][tx] = ib[(long)(r0 + ty + i * 8) * C + c0 + tx];
    __syncthreads();
    long ob = (long)blockIdx.z * sOut;
#pragma unroll
    for (int i = 0; i < 4; i++) {
        float v = t[tx][ty + i * 8];
        __nv_bfloat16 h = __float2bfloat16(v);
        __nv_bfloat16 l = __float2bfloat16(v - __bfloat162float(h));
        long o = ob + (long)(c0 + ty + i * 8) * R + r0 + tx;
        oh[o] = h; ol[o] = l;
    }
}

// ---------------------------------------------------------------------------
// Softmax over axis=1 (per column j over rows i), diag excluded, in-place fp32
// ---------------------------------------------------------------------------
__global__ __launch_bounds__(256) void softmax_dim1_k(float* __restrict__ Aw)
{
    const int j = blockIdx.x * blockDim.x + threadIdx.x;
    float* Mb = Aw + (long)blockIdx.y * NN * NN;
    float mx = -FLT_MAX;
    for (int i = 0; i < NN; i++) {
        float v = Mb[(long)i * NN + j];
        if (i != j) mx = fmaxf(mx, v);
    }
    float s = 0.f;
    for (int i = 0; i < NN; i++) {
        float v = Mb[(long)i * NN + j];
        float e = (i == j) ? 0.f : __expf(v - mx);
        s += e;
        Mb[(long)i * NN + j] = e;
    }
    float inv = 1.f / s;
    for (int i = 0; i < NN; i++) Mb[(long)i * NN + j] *= inv;
}

// ---------------------------------------------------------------------------
extern "C" void kernel_launch(void* const* d_in, const int* in_sizes, int n_in,
                              void* d_out, int out_size)
{
    const float* y  = (const float*)d_in[0];
    const float* Wk = (const float*)d_in[1];
    const float* Wq = (const float*)d_in[2];
    const float* Wv = (const float*)d_in[3];
    const float* Wo = (const float*)d_in[4];

    float* out = (float*)d_out;
    float* Aw  = out + (long)BB * NN * DD;

    __nv_bfloat16 *yh, *yl, *Wh, *Wl, *Kh, *Kl, *Qh, *Ql, *VTh, *VTl, *ATh, *ATl, *mh, *ml;
    float* Vf;
    cudaGetSymbolAddress((void**)&yh, g_yh);   cudaGetSymbolAddress((void**)&yl, g_yl);
    cudaGetSymbolAddress((void**)&Wh, g_Wh);   cudaGetSymbolAddress((void**)&Wl, g_Wl);
    cudaGetSymbolAddress((void**)&Kh, g_Kh);   cudaGetSymbolAddress((void**)&Kl, g_Kl);
    cudaGetSymbolAddress((void**)&Qh, g_Qh);   cudaGetSymbolAddress((void**)&Ql, g_Ql);
    cudaGetSymbolAddress((void**)&Vf, g_V);
    cudaGetSymbolAddress((void**)&VTh, g_VTh); cudaGetSymbolAddress((void**)&VTl, g_VTl);
    cudaGetSymbolAddress((void**)&ATh, g_ATh); cudaGetSymbolAddress((void**)&ATl, g_ATl);
    cudaGetSymbolAddress((void**)&mh, g_mh);   cudaGetSymbolAddress((void**)&ml, g_ml);

    cudaFuncSetAttribute(gemm_hmma, cudaFuncAttributeMaxDynamicSharedMemorySize, SMEMB);

    const long nd = (long)NN * DD;
    const long nn = (long)NN * NN;
    const long dd = (long)DD * DD;
    const long nY = (long)BB * NN * DD;

    // 1) splits of inputs
    splitf_k<<<(int)(nY / 1024), 256>>>(y, yh, yl, nY);
    splitf_k<<<(int)(dd / 1024), 256>>>(Wk, Wh + 0 * dd, Wl + 0 * dd, dd);
    splitf_k<<<(int)(dd / 1024), 256>>>(Wq, Wh + 1 * dd, Wl + 1 * dd, dd);
    splitf_k<<<(int)(dd / 1024), 256>>>(Wv, Wh + 2 * dd, Wl + 2 * dd, dd);
    splitf_k<<<(int)(dd / 1024), 256>>>(Wo, Wh + 3 * dd, Wl + 3 * dd, dd);

    // 2) projections (M = B*N = 8192 flat)
    {
        dim3 g(DD / 128, (BB * NN) / 128, 1);
        gemm_hmma<<<g, 256, SMEMB>>>(yh, yl, Wh + 0 * dd, Wl + 0 * dd, nullptr, Kh, Kl,
                                     DD, DD, 0, 0, 0, 1.0f, 1);
        gemm_hmma<<<g, 256, SMEMB>>>(yh, yl, Wh + 1 * dd, Wl + 1 * dd, nullptr, Qh, Ql,
                                     DD, DD, 0, 0, 0, 0.1f, 1);
        gemm_hmma<<<g, 256, SMEMB>>>(yh, yl, Wh + 2 * dd, Wl + 2 * dd, Vf, nullptr, nullptr,
                                     DD, DD, 0, 0, 0, 1.0f, 0);
    }

    // 3) logits per batch: Aw[b] = Q_b @ K_b^T  (fp32 into d_out)
    {
        dim3 g(NN / 128, NN / 128, BB);
        gemm_hmma<<<g, 256, SMEMB>>>(Qh, Ql, Kh, Kl, Aw, nullptr, nullptr,
                                     NN, DD, nd, nd, nn, 1.0f, 0);
    }

    // 4) column softmax (axis=1), diagonal excluded, in place
    {
        dim3 g(NN / 256, BB, 1);
        softmax_dim1_k<<<g, 256>>>(Aw);
    }

    // 5) transpose-splits: AwT[i][j] = Aw[j][i];  VT[d][j] = V[j][d]
    {
        dim3 g1(NN / 32, NN / 32, BB);
        tsplit_k<<<g1, dim3(32, 8)>>>(Aw, ATh, ATl, NN, NN, nn, nn);
        dim3 g2(DD / 32, NN / 32, BB);
        tsplit_k<<<g2, dim3(32, 8)>>>(Vf, VTh, VTl, NN, DD, nd, nd);
    }

    // 6) mid[b] = AwT_b @ VT_b^T  (M=1024 i, Nc=2048 d, K=1024 j) -> bf16 split
    {
        dim3 g(DD / 128, NN / 128, BB);
        gemm_hmma<<<g, 256, SMEMB>>>(ATh, ATl, VTh, VTl, nullptr, mh, ml,
                                     DD, NN, nn, nd, nd, 1.0f, 1);
    }

    // 7) out = mid @ Wo^T (flat) -> fp32 d_out
    {
        dim3 g(DD / 128, (BB * NN) / 128, 1);
        gemm_hmma<<<g, 256, SMEMB>>>(mh, ml, Wh + 3 * dd, Wl + 3 * dd, out, nullptr, nullptr,
                                     DD, DD, 0, 0, 0, 1.0f, 0);
    }
}

// round 4
// speedup vs baseline: 2.8423x; 1.0649x over previous
#include <cuda_runtime.h>
#include <cuda_bf16.h>
#include <cstdint>
#include <cfloat>
#include <math.h>

#define BB 8
#define NN 1024
#define DD 2048
#define PP (3 * DD)   // packed projection width (K|Q|V)

// ---------------------------------------------------------------------------
// Scratch (allocation-free rule: static __device__ arrays)
// ---------------------------------------------------------------------------
static __device__ __align__(16) __nv_bfloat16 g_yh[BB * NN * DD], g_yl[BB * NN * DD];
static __device__ __align__(16) __nv_bfloat16 g_Wh[4 * DD * DD], g_Wl[4 * DD * DD]; // k,q,v,o stacked
static __device__ __align__(16) __nv_bfloat16 g_Ph[BB * NN * PP], g_Pl[BB * NN * PP]; // K|Q|V packed
static __device__ __align__(16) __nv_bfloat16 g_VTh[BB * NN * DD], g_VTl[BB * NN * DD];
static __device__ __align__(16) __nv_bfloat16 g_ATh[BB * NN * NN], g_ATl[BB * NN * NN];
static __device__ __align__(16) __nv_bfloat16 g_mh[BB * NN * DD], g_ml[BB * NN * DD];

// ---------------------------------------------------------------------------
// Baseline-PTX helpers (sm_103 non-'a': mma.sync / ldmatrix / cp.async)
// ---------------------------------------------------------------------------
__device__ __forceinline__ uint32_t smem_u32(const void* p) {
    uint32_t a;
    asm("{ .reg .u64 t; cvta.to.shared.u64 t, %1; cvt.u32.u64 %0, t; }" : "=r"(a) : "l"(p));
    return a;
}
__device__ __forceinline__ void cp16(uint32_t dst, const void* src) {
    asm volatile("cp.async.cg.shared.global [%0], [%1], 16;" :: "r"(dst), "l"(src) : "memory");
}
#define CP_COMMIT() asm volatile("cp.async.commit_group;" ::: "memory")
#define CP_WAIT1()  asm volatile("cp.async.wait_group 1;" ::: "memory")

__device__ __forceinline__ void ldm_x4(uint32_t& r0, uint32_t& r1, uint32_t& r2, uint32_t& r3,
                                       uint32_t addr) {
    asm volatile("ldmatrix.sync.aligned.m8n8.x4.shared.b16 {%0,%1,%2,%3}, [%4];"
                 : "=r"(r0), "=r"(r1), "=r"(r2), "=r"(r3) : "r"(addr));
}
__device__ __forceinline__ void mma_bf16(float* c, const uint32_t* a, const uint32_t* b) {
    asm volatile(
        "mma.sync.aligned.m16n8k16.row.col.f32.bf16.bf16.f32 "
        "{%0,%1,%2,%3}, {%4,%5,%6,%7}, {%8,%9}, {%0,%1,%2,%3};"
        : "+f"(c[0]), "+f"(c[1]), "+f"(c[2]), "+f"(c[3])
        : "r"(a[0]), "r"(a[1]), "r"(a[2]), "r"(a[3]), "r"(b[0]), "r"(b[1]));
}

// ---------------------------------------------------------------------------
// HMMA GEMM:  C[M,Nc] = alpha * A[M,K] * B[Nc,K]^T   (bf16 hi/lo, fp32 acc)
// tile 128x128x32, 256 threads (8 warps, 64x32 each), cp.async double buffer,
// 80B-padded SMEM rows (conflict-free ldmatrix). 2 CTAs/SM.
// mode 0: fp32 C.   mode 1: bf16 hi/lo split C.
// ---------------------------------------------------------------------------
#define ROWB   80
#define MATB   (128 * ROWB)
#define STAGEB (4 * MATB)
#define SMEMB  (2 * STAGEB)     // 81920 B

__global__ __launch_bounds__(256, 2) void gemm_hmma(
    const __nv_bfloat16* __restrict__ Ah, const __nv_bfloat16* __restrict__ Al,
    const __nv_bfloat16* __restrict__ Bh, const __nv_bfloat16* __restrict__ Bl,
    float* __restrict__ Cf, __nv_bfloat16* __restrict__ Ch, __nv_bfloat16* __restrict__ Cl,
    int Nc, int K, int lda, int ldb, long sA, long sB, long sC, float alpha, int mode)
{
    extern __shared__ char smem[];
    const uint32_t sb = smem_u32(smem);

    const int tid  = threadIdx.x;
    const int wid  = tid >> 5;
    const int lane = tid & 31;
    const int m0 = blockIdx.y * 128, n0 = blockIdx.x * 128;

    const __nv_bfloat16* pA[2] = { Ah + (long)blockIdx.z * sA + (long)m0 * lda,
                                   Al + (long)blockIdx.z * sA + (long)m0 * lda };
    const __nv_bfloat16* pB[2] = { Bh + (long)blockIdx.z * sB + (long)n0 * ldb,
                                   Bl + (long)blockIdx.z * sB + (long)n0 * ldb };
    const long zC = (long)blockIdx.z * sC;

    const int r0c = tid >> 2,         q0 = tid & 3;
    const int r1c = (tid + 256) >> 2, q1 = tid & 3;

    const int wm0 = (wid >> 2) * 64;
    const int wn0 = (wid & 3) * 32;

    const int a_row  = lane & 15;
    const int a_koff = (lane >> 4) * 16;
    const int b_row  = ((lane >> 3) & 2) * 4 + (lane & 7);
    const int b_koff = ((lane >> 3) & 1) * 16;

    float acc[4][4][4];
#pragma unroll
    for (int i = 0; i < 4; i++)
#pragma unroll
        for (int j = 0; j < 4; j++)
#pragma unroll
            for (int k = 0; k < 4; k++) acc[i][j][k] = 0.f;

    const int nst = K >> 5;

    // stage 0
    {
        uint32_t s0 = sb;
#pragma unroll
        for (int m = 0; m < 2; m++) {
            cp16(s0 + m * MATB + r0c * ROWB + q0 * 16, pA[m] + (long)r0c * lda + q0 * 8);
            cp16(s0 + m * MATB + r1c * ROWB + q1 * 16, pA[m] + (long)r1c * lda + q1 * 8);
            cp16(s0 + (2 + m) * MATB + r0c * ROWB + q0 * 16, pB[m] + (long)r0c * ldb + q0 * 8);
            cp16(s0 + (2 + m) * MATB + r1c * ROWB + q1 * 16, pB[m] + (long)r1c * ldb + q1 * 8);
        }
        CP_COMMIT();
    }

    for (int c = 0; c < nst; c++) {
        if (c + 1 < nst) {
            const int k0 = (c + 1) << 5;
            uint32_t s1 = sb + ((c + 1) & 1) * STAGEB;
#pragma unroll
            for (int m = 0; m < 2; m++) {
                cp16(s1 + m * MATB + r0c * ROWB + q0 * 16, pA[m] + (long)r0c * lda + k0 + q0 * 8);
                cp16(s1 + m * MATB + r1c * ROWB + q1 * 16, pA[m] + (long)r1c * lda + k0 + q1 * 8);
                cp16(s1 + (2 + m) * MATB + r0c * ROWB + q0 * 16, pB[m] + (long)r0c * ldb + k0 + q0 * 8);
                cp16(s1 + (2 + m) * MATB + r1c * ROWB + q1 * 16, pB[m] + (long)r1c * ldb + k0 + q1 * 8);
            }
        }
        CP_COMMIT();
        CP_WAIT1();
        __syncthreads();

        const uint32_t st = sb + (c & 1) * STAGEB;
        const uint32_t aHb = st + 0 * MATB + (wm0 + a_row) * ROWB + a_koff;
        const uint32_t aLb = st + 1 * MATB + (wm0 + a_row) * ROWB + a_koff;
        const uint32_t bHb = st + 2 * MATB + (wn0 + b_row) * ROWB + b_koff;
        const uint32_t bLb = st + 3 * MATB + (wn0 + b_row) * ROWB + b_koff;

#pragma unroll
        for (int s = 0; s < 2; s++) {
            const int sk = s * 32;
            uint32_t bh[2][4], bl[2][4];
#pragma unroll
            for (int nb = 0; nb < 2; nb++) {
                ldm_x4(bh[nb][0], bh[nb][1], bh[nb][2], bh[nb][3], bHb + nb * 16 * ROWB + sk);
                ldm_x4(bl[nb][0], bl[nb][1], bl[nb][2], bl[nb][3], bLb + nb * 16 * ROWB + sk);
            }
#pragma unroll
            for (int mi = 0; mi < 4; mi++) {
                uint32_t ah[4], al[4];
                ldm_x4(ah[0], ah[1], ah[2], ah[3], aHb + mi * 16 * ROWB + sk);
                ldm_x4(al[0], al[1], al[2], al[3], aLb + mi * 16 * ROWB + sk);
#pragma unroll
                for (int ni = 0; ni < 4; ni++) {
                    const uint32_t* bhf = &bh[ni >> 1][(ni & 1) * 2];
                    const uint32_t* blf = &bl[ni >> 1][(ni & 1) * 2];
                    mma_bf16(acc[mi][ni], ah, bhf);
                    mma_bf16(acc[mi][ni], ah, blf);
                    mma_bf16(acc[mi][ni], al, bhf);
                }
            }
        }
        __syncthreads();
    }

    // epilogue
    const int er = lane >> 2;
    const int ec = (lane & 3) * 2;
#pragma unroll
    for (int mi = 0; mi < 4; mi++) {
#pragma unroll
        for (int ni = 0; ni < 4; ni++) {
            const int row = m0 + wm0 + 16 * mi + er;
            const int col = n0 + wn0 + 8 * ni + ec;
            float v0 = acc[mi][ni][0] * alpha, v1 = acc[mi][ni][1] * alpha;
            float v2 = acc[mi][ni][2] * alpha, v3 = acc[mi][ni][3] * alpha;
            if (mode == 0) {
                *reinterpret_cast<float2*>(Cf + zC + (long)row * Nc + col) = make_float2(v0, v1);
                *reinterpret_cast<float2*>(Cf + zC + (long)(row + 8) * Nc + col) = make_float2(v2, v3);
            } else {
                __nv_bfloat162 h, l;
                h.x = __float2bfloat16(v0); l.x = __float2bfloat16(v0 - __bfloat162float(h.x));
                h.y = __float2bfloat16(v1); l.y = __float2bfloat16(v1 - __bfloat162float(h.y));
                *reinterpret_cast<__nv_bfloat162*>(Ch + zC + (long)row * Nc + col) = h;
                *reinterpret_cast<__nv_bfloat162*>(Cl + zC + (long)row * Nc + col) = l;
                h.x = __float2bfloat16(v2); l.x = __float2bfloat16(v2 - __bfloat162float(h.x));
                h.y = __float2bfloat16(v3); l.y = __float2bfloat16(v3 - __bfloat162float(h.y));
                *reinterpret_cast<__nv_bfloat162*>(Ch + zC + (long)(row + 8) * Nc + col) = h;
                *reinterpret_cast<__nv_bfloat162*>(Cl + zC + (long)(row + 8) * Nc + col) = l;
            }
        }
    }
}

// ---------------------------------------------------------------------------
// fp32 -> bf16 hi/lo elementwise split (with scale folded in)
// ---------------------------------------------------------------------------
__global__ __launch_bounds__(256) void splitf_k(const float* __restrict__ x,
    __nv_bfloat16* __restrict__ hi, __nv_bfloat16* __restrict__ lo, long n, float scale)
{
    long i = ((long)blockIdx.x * 256 + threadIdx.x) * 4;
    if (i >= n) return;
    float4 v = *reinterpret_cast<const float4*>(x + i);
    v.x *= scale; v.y *= scale; v.z *= scale; v.w *= scale;
    __nv_bfloat162 h01, h23, l01, l23;
    h01.x = __float2bfloat16(v.x); l01.x = __float2bfloat16(v.x - __bfloat162float(h01.x));
    h01.y = __float2bfloat16(v.y); l01.y = __float2bfloat16(v.y - __bfloat162float(h01.y));
    h23.x = __float2bfloat16(v.z); l23.x = __float2bfloat16(v.z - __bfloat162float(h23.x));
    h23.y = __float2bfloat16(v.w); l23.y = __float2bfloat16(v.w - __bfloat162float(h23.y));
    uint2 hv, lv;
    hv.x = *reinterpret_cast<uint32_t*>(&h01); hv.y = *reinterpret_cast<uint32_t*>(&h23);
    lv.x = *reinterpret_cast<uint32_t*>(&l01); lv.y = *reinterpret_cast<uint32_t*>(&l23);
    *reinterpret_cast<uint2*>(hi + i) = hv;
    *reinterpret_cast<uint2*>(lo + i) = lv;
}

// ---------------------------------------------------------------------------
// bf16 transpose (hi & lo in one pass): out[c][r] = in[r][c]
// in: [R x C] with row stride ldin; out: [C x R]
// ---------------------------------------------------------------------------
__global__ __launch_bounds__(256) void tbf16_k(
    const __nv_bfloat16* __restrict__ ih, const __nv_bfloat16* __restrict__ il,
    __nv_bfloat16* __restrict__ oh, __nv_bfloat16* __restrict__ ol,
    int R, int C, int ldin, long sIn, long sOut)
{
    __shared__ __nv_bfloat16 th[32][33], tl[32][33];
    long ibo = (long)blockIdx.z * sIn;
    int r0 = blockIdx.y * 32, c0 = blockIdx.x * 32;
    int tx = threadIdx.x, ty = threadIdx.y;
#pragma unroll
    for (int i = 0; i < 4; i++) {
        long o = ibo + (long)(r0 + ty + i * 8) * ldin + c0 + tx;
        th[ty + i * 8][tx] = ih[o];
        tl[ty + i * 8][tx] = il[o];
    }
    __syncthreads();
    long ob = (long)blockIdx.z * sOut;
#pragma unroll
    for (int i = 0; i < 4; i++) {
        long o = ob + (long)(c0 + ty + i * 8) * R + r0 + tx;
        oh[o] = th[tx][ty + i * 8];
        ol[o] = tl[tx][ty + i * 8];
    }
}

// ---------------------------------------------------------------------------
// transpose + split fp32 -> bf16 hi/lo: out[c][r] = split(in[r][c])
// ---------------------------------------------------------------------------
__global__ __launch_bounds__(256) void tsplit_k(const float* __restrict__ in,
    __nv_bfloat16* __restrict__ oh, __nv_bfloat16* __restrict__ ol,
    int R, int C, long sIn, long sOut)
{
    __shared__ float t[32][33];
    const float* ib = in + (long)blockIdx.z * sIn;
    int r0 = blockIdx.y * 32, c0 = blockIdx.x * 32;
    int tx = threadIdx.x, ty = threadIdx.y;
#pragma unroll
    for (int i = 0; i < 4; i++)
        t[ty + i * 8][tx] = ib[(long)(r0 + ty + i * 8) * C + c0 + tx];
    __syncthreads();
    long ob = (long)blockIdx.z * sOut;
#pragma unroll
    for (int i = 0; i < 4; i++) {
        float v = t[tx][ty + i * 8];
        __nv_bfloat16 h = __float2bfloat16(v);
        __nv_bfloat16 l = __float2bfloat16(v - __bfloat162float(h));
        long o = ob + (long)(c0 + ty + i * 8) * R + r0 + tx;
        oh[o] = h; ol[o] = l;
    }
}

// ---------------------------------------------------------------------------
// Softmax over axis=1 (per column j over rows i), diag excluded, in-place fp32
// ---------------------------------------------------------------------------
__global__ __launch_bounds__(256) void softmax_dim1_k(float* __restrict__ Aw)
{
    const int j = blockIdx.x * blockDim.x + threadIdx.x;
    float* Mb = Aw + (long)blockIdx.y * NN * NN;
    float mx = -FLT_MAX;
    for (int i = 0; i < NN; i++) {
        float v = Mb[(long)i * NN + j];
        if (i != j) mx = fmaxf(mx, v);
    }
    float s = 0.f;
    for (int i = 0; i < NN; i++) {
        float v = Mb[(long)i * NN + j];
        float e = (i == j) ? 0.f : __expf(v - mx);
        s += e;
        Mb[(long)i * NN + j] = e;
    }
    float inv = 1.f / s;
    for (int i = 0; i < NN; i++) Mb[(long)i * NN + j] *= inv;
}

// ---------------------------------------------------------------------------
extern "C" void kernel_launch(void* const* d_in, const int* in_sizes, int n_in,
                              void* d_out, int out_size)
{
    const float* y  = (const float*)d_in[0];
    const float* Wk = (const float*)d_in[1];
    const float* Wq = (const float*)d_in[2];
    const float* Wv = (const float*)d_in[3];
    const float* Wo = (const float*)d_in[4];

    float* out = (float*)d_out;
    float* Aw  = out + (long)BB * NN * DD;

    __nv_bfloat16 *yh, *yl, *Wh, *Wl, *Ph, *Pl, *VTh, *VTl, *ATh, *ATl, *mh, *ml;
    cudaGetSymbolAddress((void**)&yh, g_yh);   cudaGetSymbolAddress((void**)&yl, g_yl);
    cudaGetSymbolAddress((void**)&Wh, g_Wh);   cudaGetSymbolAddress((void**)&Wl, g_Wl);
    cudaGetSymbolAddress((void**)&Ph, g_Ph);   cudaGetSymbolAddress((void**)&Pl, g_Pl);
    cudaGetSymbolAddress((void**)&VTh, g_VTh); cudaGetSymbolAddress((void**)&VTl, g_VTl);
    cudaGetSymbolAddress((void**)&ATh, g_ATh); cudaGetSymbolAddress((void**)&ATl, g_ATl);
    cudaGetSymbolAddress((void**)&mh, g_mh);   cudaGetSymbolAddress((void**)&ml, g_ml);

    cudaFuncSetAttribute(gemm_hmma, cudaFuncAttributeMaxDynamicSharedMemorySize, SMEMB);

    const long nd = (long)NN * DD;
    const long np = (long)NN * PP;
    const long nn = (long)NN * NN;
    const long dd = (long)DD * DD;
    const long nY = (long)BB * NN * DD;

    // 1) splits: y, and W stacked [Wk; 0.1*Wq; Wv; Wo]
    splitf_k<<<(int)(nY / 1024), 256>>>(y, yh, yl, nY, 1.0f);
    splitf_k<<<(int)(dd / 1024), 256>>>(Wk, Wh + 0 * dd, Wl + 0 * dd, dd, 1.0f);
    splitf_k<<<(int)(dd / 1024), 256>>>(Wq, Wh + 1 * dd, Wl + 1 * dd, dd, 0.1f);
    splitf_k<<<(int)(dd / 1024), 256>>>(Wv, Wh + 2 * dd, Wl + 2 * dd, dd, 1.0f);
    splitf_k<<<(int)(dd / 1024), 256>>>(Wo, Wh + 3 * dd, Wl + 3 * dd, dd, 1.0f);

    // 2) fused projection: P[8192, 6144] = y @ [Wk;0.1Wq;Wv]^T  -> bf16 split
    {
        dim3 g(PP / 128, (BB * NN) / 128, 1);
        gemm_hmma<<<g, 256, SMEMB>>>(yh, yl, Wh, Wl, nullptr, Ph, Pl,
                                     PP, DD, DD, DD, 0, 0, 0, 1.0f, 1);
    }

    // 3) logits per batch: Aw[b] = Q_b @ K_b^T (fp32 into d_out)
    //    Q = P cols [2048,4096), K = P cols [0,2048); row stride PP
    {
        dim3 g(NN / 128, NN / 128, BB);
        gemm_hmma<<<g, 256, SMEMB>>>(Ph + DD, Pl + DD, Ph, Pl, Aw, nullptr, nullptr,
                                     NN, DD, PP, PP, np, np, nn, 1.0f, 0);
    }

    // 4) column softmax (axis=1), diagonal excluded, in place
    {
        dim3 g(NN / 256, BB, 1);
        softmax_dim1_k<<<g, 256>>>(Aw);
    }

    // 5) transposes: AwT (fp32 -> split), VT (bf16 hi/lo direct)
    {
        dim3 g1(NN / 32, NN / 32, BB);
        tsplit_k<<<g1, dim3(32, 8)>>>(Aw, ATh, ATl, NN, NN, nn, nn);
        dim3 g2(DD / 32, NN / 32, BB);
        tbf16_k<<<g2, dim3(32, 8)>>>(Ph + 2 * DD, Pl + 2 * DD, VTh, VTl,
                                     NN, DD, PP, np, nd);
    }

    // 6) mid[b] = AwT_b @ VT_b^T -> bf16 split
    {
        dim3 g(DD / 128, NN / 128, BB);
        gemm_hmma<<<g, 256, SMEMB>>>(ATh, ATl, VTh, VTl, nullptr, mh, ml,
                                     DD, NN, NN, NN, nn, nd, nd, 1.0f, 1);
    }

    // 7) out = mid @ Wo^T (flat) -> fp32 d_out
    {
        dim3 g(DD / 128, (BB * NN) / 128, 1);
        gemm_hmma<<<g, 256, SMEMB>>>(mh, ml, Wh + 3 * dd, Wl + 3 * dd, out, nullptr, nullptr,
                                     DD, DD, DD, DD, 0, 0, 0, 1.0f, 0);
    }
}

// round 5
// speedup vs baseline: 3.0439x; 1.0709x over previous
#include <cuda_runtime.h>
#include <cuda_bf16.h>
#include <cstdint>
#include <cfloat>
#include <math.h>

#define BB 8
#define NN 1024
#define DD 2048
#define PP (3 * DD)   // packed projection width (K|Q|V)

// ---------------------------------------------------------------------------
// Scratch (allocation-free rule: static __device__ arrays)
// ---------------------------------------------------------------------------
static __device__ __align__(16) __nv_bfloat16 g_yh[BB * NN * DD], g_yl[BB * NN * DD];
static __device__ __align__(16) __nv_bfloat16 g_Wh[4 * DD * DD], g_Wl[4 * DD * DD]; // k,q,v,o stacked
static __device__ __align__(16) __nv_bfloat16 g_Ph[BB * NN * PP], g_Pl[BB * NN * PP]; // K|Q|V packed
static __device__ __align__(16) __nv_bfloat16 g_VTh[BB * NN * DD], g_VTl[BB * NN * DD];
static __device__ __align__(16) __nv_bfloat16 g_ATh[BB * NN * NN], g_ATl[BB * NN * NN];
static __device__ __align__(16) __nv_bfloat16 g_mh[BB * NN * DD], g_ml[BB * NN * DD];
static __device__ __align__(16) float         g_inv[BB * NN];

// ---------------------------------------------------------------------------
// Baseline-PTX helpers (sm_103 non-'a': mma.sync / ldmatrix / cp.async)
// ---------------------------------------------------------------------------
__device__ __forceinline__ uint32_t smem_u32(const void* p) {
    uint32_t a;
    asm("{ .reg .u64 t; cvta.to.shared.u64 t, %1; cvt.u32.u64 %0, t; }" : "=r"(a) : "l"(p));
    return a;
}
__device__ __forceinline__ void cp16(uint32_t dst, const void* src) {
    asm volatile("cp.async.cg.shared.global [%0], [%1], 16;" :: "r"(dst), "l"(src) : "memory");
}
#define CP_COMMIT() asm volatile("cp.async.commit_group;" ::: "memory")
#define CP_WAIT1()  asm volatile("cp.async.wait_group 1;" ::: "memory")

__device__ __forceinline__ void ldm_x4(uint32_t& r0, uint32_t& r1, uint32_t& r2, uint32_t& r3,
                                       uint32_t addr) {
    asm volatile("ldmatrix.sync.aligned.m8n8.x4.shared.b16 {%0,%1,%2,%3}, [%4];"
                 : "=r"(r0), "=r"(r1), "=r"(r2), "=r"(r3) : "r"(addr));
}
__device__ __forceinline__ void mma_bf16(float* c, const uint32_t* a, const uint32_t* b) {
    asm volatile(
        "mma.sync.aligned.m16n8k16.row.col.f32.bf16.bf16.f32 "
        "{%0,%1,%2,%3}, {%4,%5,%6,%7}, {%8,%9}, {%0,%1,%2,%3};"
        : "+f"(c[0]), "+f"(c[1]), "+f"(c[2]), "+f"(c[3])
        : "r"(a[0]), "r"(a[1]), "r"(a[2]), "r"(a[3]), "r"(b[0]), "r"(b[1]));
}

// ---------------------------------------------------------------------------
// HMMA GEMM:  C[M,Nc] = alpha * A[M,K] * B[Nc,K]^T   (bf16 hi/lo, fp32 acc)
// tile 128x128x32, 256 threads (8 warps, 64x32 each), cp.async double buffer,
// 80B-padded SMEM rows (conflict-free ldmatrix). 2 CTAs/SM.
// mode 0: fp32 C.  mode 1: bf16 hi/lo split C.  mode 2: fp32 exp(C).
// ---------------------------------------------------------------------------
#define ROWB   80
#define MATB   (128 * ROWB)
#define STAGEB (4 * MATB)
#define SMEMB  (2 * STAGEB)     // 81920 B

__global__ __launch_bounds__(256, 2) void gemm_hmma(
    const __nv_bfloat16* __restrict__ Ah, const __nv_bfloat16* __restrict__ Al,
    const __nv_bfloat16* __restrict__ Bh, const __nv_bfloat16* __restrict__ Bl,
    float* __restrict__ Cf, __nv_bfloat16* __restrict__ Ch, __nv_bfloat16* __restrict__ Cl,
    int Nc, int K, int lda, int ldb, long sA, long sB, long sC, float alpha, int mode)
{
    extern __shared__ char smem[];
    const uint32_t sb = smem_u32(smem);

    const int tid  = threadIdx.x;
    const int wid  = tid >> 5;
    const int lane = tid & 31;
    const int m0 = blockIdx.y * 128, n0 = blockIdx.x * 128;

    const __nv_bfloat16* pA[2] = { Ah + (long)blockIdx.z * sA + (long)m0 * lda,
                                   Al + (long)blockIdx.z * sA + (long)m0 * lda };
    const __nv_bfloat16* pB[2] = { Bh + (long)blockIdx.z * sB + (long)n0 * ldb,
                                   Bl + (long)blockIdx.z * sB + (long)n0 * ldb };
    const long zC = (long)blockIdx.z * sC;

    const int r0c = tid >> 2,         q0 = tid & 3;
    const int r1c = (tid + 256) >> 2, q1 = tid & 3;

    const int wm0 = (wid >> 2) * 64;
    const int wn0 = (wid & 3) * 32;

    const int a_row  = lane & 15;
    const int a_koff = (lane >> 4) * 16;
    const int b_row  = ((lane >> 3) & 2) * 4 + (lane & 7);
    const int b_koff = ((lane >> 3) & 1) * 16;

    float acc[4][4][4];
#pragma unroll
    for (int i = 0; i < 4; i++)
#pragma unroll
        for (int j = 0; j < 4; j++)
#pragma unroll
            for (int k = 0; k < 4; k++) acc[i][j][k] = 0.f;

    const int nst = K >> 5;

    // stage 0
    {
        uint32_t s0 = sb;
#pragma unroll
        for (int m = 0; m < 2; m++) {
            cp16(s0 + m * MATB + r0c * ROWB + q0 * 16, pA[m] + (long)r0c * lda + q0 * 8);
            cp16(s0 + m * MATB + r1c * ROWB + q1 * 16, pA[m] + (long)r1c * lda + q1 * 8);
            cp16(s0 + (2 + m) * MATB + r0c * ROWB + q0 * 16, pB[m] + (long)r0c * ldb + q0 * 8);
            cp16(s0 + (2 + m) * MATB + r1c * ROWB + q1 * 16, pB[m] + (long)r1c * ldb + q1 * 8);
        }
        CP_COMMIT();
    }

    for (int c = 0; c < nst; c++) {
        if (c + 1 < nst) {
            const int k0 = (c + 1) << 5;
            uint32_t s1 = sb + ((c + 1) & 1) * STAGEB;
#pragma unroll
            for (int m = 0; m < 2; m++) {
                cp16(s1 + m * MATB + r0c * ROWB + q0 * 16, pA[m] + (long)r0c * lda + k0 + q0 * 8);
                cp16(s1 + m * MATB + r1c * ROWB + q1 * 16, pA[m] + (long)r1c * lda + k0 + q1 * 8);
                cp16(s1 + (2 + m) * MATB + r0c * ROWB + q0 * 16, pB[m] + (long)r0c * ldb + k0 + q0 * 8);
                cp16(s1 + (2 + m) * MATB + r1c * ROWB + q1 * 16, pB[m] + (long)r1c * ldb + k0 + q1 * 8);
            }
        }
        CP_COMMIT();
        CP_WAIT1();
        __syncthreads();

        const uint32_t st = sb + (c & 1) * STAGEB;
        const uint32_t aHb = st + 0 * MATB + (wm0 + a_row) * ROWB + a_koff;
        const uint32_t aLb = st + 1 * MATB + (wm0 + a_row) * ROWB + a_koff;
        const uint32_t bHb = st + 2 * MATB + (wn0 + b_row) * ROWB + b_koff;
        const uint32_t bLb = st + 3 * MATB + (wn0 + b_row) * ROWB + b_koff;

#pragma unroll
        for (int s = 0; s < 2; s++) {
            const int sk = s * 32;
            uint32_t bh[2][4], bl[2][4];
#pragma unroll
            for (int nb = 0; nb < 2; nb++) {
                ldm_x4(bh[nb][0], bh[nb][1], bh[nb][2], bh[nb][3], bHb + nb * 16 * ROWB + sk);
                ldm_x4(bl[nb][0], bl[nb][1], bl[nb][2], bl[nb][3], bLb + nb * 16 * ROWB + sk);
            }
#pragma unroll
            for (int mi = 0; mi < 4; mi++) {
                uint32_t ah[4], al[4];
                ldm_x4(ah[0], ah[1], ah[2], ah[3], aHb + mi * 16 * ROWB + sk);
                ldm_x4(al[0], al[1], al[2], al[3], aLb + mi * 16 * ROWB + sk);
#pragma unroll
                for (int ni = 0; ni < 4; ni++) {
                    const uint32_t* bhf = &bh[ni >> 1][(ni & 1) * 2];
                    const uint32_t* blf = &bl[ni >> 1][(ni & 1) * 2];
                    mma_bf16(acc[mi][ni], ah, bhf);
                    mma_bf16(acc[mi][ni], ah, blf);
                    mma_bf16(acc[mi][ni], al, bhf);
                }
            }
        }
        __syncthreads();
    }

    // epilogue
    const int er = lane >> 2;
    const int ec = (lane & 3) * 2;
#pragma unroll
    for (int mi = 0; mi < 4; mi++) {
#pragma unroll
        for (int ni = 0; ni < 4; ni++) {
            const int row = m0 + wm0 + 16 * mi + er;
            const int col = n0 + wn0 + 8 * ni + ec;
            float v0 = acc[mi][ni][0] * alpha, v1 = acc[mi][ni][1] * alpha;
            float v2 = acc[mi][ni][2] * alpha, v3 = acc[mi][ni][3] * alpha;
            if (mode == 0) {
                *reinterpret_cast<float2*>(Cf + zC + (long)row * Nc + col) = make_float2(v0, v1);
                *reinterpret_cast<float2*>(Cf + zC + (long)(row + 8) * Nc + col) = make_float2(v2, v3);
            } else if (mode == 2) {
                *reinterpret_cast<float2*>(Cf + zC + (long)row * Nc + col) =
                    make_float2(__expf(v0), __expf(v1));
                *reinterpret_cast<float2*>(Cf + zC + (long)(row + 8) * Nc + col) =
                    make_float2(__expf(v2), __expf(v3));
            } else {
                __nv_bfloat162 h, l;
                h.x = __float2bfloat16(v0); l.x = __float2bfloat16(v0 - __bfloat162float(h.x));
                h.y = __float2bfloat16(v1); l.y = __float2bfloat16(v1 - __bfloat162float(h.y));
                *reinterpret_cast<__nv_bfloat162*>(Ch + zC + (long)row * Nc + col) = h;
                *reinterpret_cast<__nv_bfloat162*>(Cl + zC + (long)row * Nc + col) = l;
                h.x = __float2bfloat16(v2); l.x = __float2bfloat16(v2 - __bfloat162float(h.x));
                h.y = __float2bfloat16(v3); l.y = __float2bfloat16(v3 - __bfloat162float(h.y));
                *reinterpret_cast<__nv_bfloat162*>(Ch + zC + (long)(row + 8) * Nc + col) = h;
                *reinterpret_cast<__nv_bfloat162*>(Cl + zC + (long)(row + 8) * Nc + col) = l;
            }
        }
    }
}

// ---------------------------------------------------------------------------
// fp32 -> bf16 hi/lo elementwise split (y)
// ---------------------------------------------------------------------------
__global__ __launch_bounds__(256) void splitf_k(const float* __restrict__ x,
    __nv_bfloat16* __restrict__ hi, __nv_bfloat16* __restrict__ lo, long n)
{
    long i = ((long)blockIdx.x * 256 + threadIdx.x) * 4;
    if (i >= n) return;
    float4 v = *reinterpret_cast<const float4*>(x + i);
    __nv_bfloat162 h01, h23, l01, l23;
    h01.x = __float2bfloat16(v.x); l01.x = __float2bfloat16(v.x - __bfloat162float(h01.x));
    h01.y = __float2bfloat16(v.y); l01.y = __float2bfloat16(v.y - __bfloat162float(h01.y));
    h23.x = __float2bfloat16(v.z); l23.x = __float2bfloat16(v.z - __bfloat162float(h23.x));
    h23.y = __float2bfloat16(v.w); l23.y = __float2bfloat16(v.w - __bfloat162float(h23.y));
    uint2 hv, lv;
    hv.x = *reinterpret_cast<uint32_t*>(&h01); hv.y = *reinterpret_cast<uint32_t*>(&h23);
    lv.x = *reinterpret_cast<uint32_t*>(&l01); lv.y = *reinterpret_cast<uint32_t*>(&l23);
    *reinterpret_cast<uint2*>(hi + i) = hv;
    *reinterpret_cast<uint2*>(lo + i) = lv;
}

// ---------------------------------------------------------------------------
// 4 weight matrices split in one launch (z selects source; Wq scaled by 0.1)
// ---------------------------------------------------------------------------
__global__ __launch_bounds__(256) void splitW_k(
    const float* __restrict__ w0, const float* __restrict__ w1,
    const float* __restrict__ w2, const float* __restrict__ w3,
    __nv_bfloat16* __restrict__ hi, __nv_bfloat16* __restrict__ lo)
{
    const int z = blockIdx.z;
    const float* src = (z == 0) ? w0 : (z == 1) ? w1 : (z == 2) ? w2 : w3;
    const float scale = (z == 1) ? 0.1f : 1.0f;
    const long dd = (long)DD * DD;
    long i = ((long)blockIdx.x * 256 + threadIdx.x) * 4;
    if (i >= dd) return;
    float4 v = *reinterpret_cast<const float4*>(src + i);
    v.x *= scale; v.y *= scale; v.z *= scale; v.w *= scale;
    __nv_bfloat162 h01, h23, l01, l23;
    h01.x = __float2bfloat16(v.x); l01.x = __float2bfloat16(v.x - __bfloat162float(h01.x));
    h01.y = __float2bfloat16(v.y); l01.y = __float2bfloat16(v.y - __bfloat162float(h01.y));
    h23.x = __float2bfloat16(v.z); l23.x = __float2bfloat16(v.z - __bfloat162float(h23.x));
    h23.y = __float2bfloat16(v.w); l23.y = __float2bfloat16(v.w - __bfloat162float(h23.y));
    long o = z * dd + i;
    uint2 hv, lv;
    hv.x = *reinterpret_cast<uint32_t*>(&h01); hv.y = *reinterpret_cast<uint32_t*>(&h23);
    lv.x = *reinterpret_cast<uint32_t*>(&l01); lv.y = *reinterpret_cast<uint32_t*>(&l23);
    *reinterpret_cast<uint2*>(hi + o) = hv;
    *reinterpret_cast<uint2*>(lo + o) = lv;
}

// ---------------------------------------------------------------------------
// Column sums of exp-logits (diag excluded) -> inv[b][j] = 1/sum
// ---------------------------------------------------------------------------
__global__ __launch_bounds__(256) void colsum_k(const float* __restrict__ Aw,
                                                float* __restrict__ inv)
{
    const int j = blockIdx.x * blockDim.x + threadIdx.x;
    const float* Mb = Aw + (long)blockIdx.y * NN * NN;
    float s0 = 0.f, s1 = 0.f, s2 = 0.f, s3 = 0.f;
#pragma unroll 4
    for (int i = 0; i < NN; i += 4) {
        s0 += Mb[(long)(i + 0) * NN + j];
        s1 += Mb[(long)(i + 1) * NN + j];
        s2 += Mb[(long)(i + 2) * NN + j];
        s3 += Mb[(long)(i + 3) * NN + j];
    }
    float s = (s0 + s1) + (s2 + s3);
    s -= Mb[(long)j * NN + j];   // exclude diagonal junk term
    inv[blockIdx.y * NN + j] = 1.f / s;
}

// ---------------------------------------------------------------------------
// Fused: normalize exp-Aw (write back fp32, diag=0) + transpose + bf16 split.
// AT[j][i] = Aw[i][j] * inv[j]  (diag 0)
// ---------------------------------------------------------------------------
__global__ __launch_bounds__(256) void normtsplit_k(float* __restrict__ Aw,
    const float* __restrict__ inv,
    __nv_bfloat16* __restrict__ oh, __nv_bfloat16* __restrict__ ol)
{
    __shared__ float t[32][33];
    const long nn = (long)NN * NN;
    float* Mb = Aw + (long)blockIdx.z * nn;
    const float* ib = inv + (long)blockIdx.z * NN;
    int r0 = blockIdx.y * 32, c0 = blockIdx.x * 32;
    int tx = threadIdx.x, ty = threadIdx.y;
    const float sc = ib[c0 + tx];           // normalization for column c0+tx
#pragma unroll
    for (int i = 0; i < 4; i++) {
        int r = r0 + ty + i * 8;
        long o = (long)r * NN + c0 + tx;
        float v = Mb[o] * sc;
        if (r == c0 + tx) v = 0.f;
        Mb[o] = v;                          // write back normalized weights
        t[ty + i * 8][tx] = v;
    }
    __syncthreads();
    long ob = (long)blockIdx.z * nn;
#pragma unroll
    for (int i = 0; i < 4; i++) {
        float v = t[tx][ty + i * 8];
        __nv_bfloat16 h = __float2bfloat16(v);
        __nv_bfloat16 l = __float2bfloat16(v - __bfloat162float(h));
        long o = ob + (long)(c0 + ty + i * 8) * NN + r0 + tx;
        oh[o] = h; ol[o] = l;
    }
}

// ---------------------------------------------------------------------------
// bf16 transpose (hi & lo in one pass): out[c][r] = in[r][c]
// ---------------------------------------------------------------------------
__global__ __launch_bounds__(256) void tbf16_k(
    const __nv_bfloat16* __restrict__ ih, const __nv_bfloat16* __restrict__ il,
    __nv_bfloat16* __restrict__ oh, __nv_bfloat16* __restrict__ ol,
    int R, int C, int ldin, long sIn, long sOut)
{
    __shared__ __nv_bfloat16 th[32][33], tl[32][33];
    long ibo = (long)blockIdx.z * sIn;
    int r0 = blockIdx.y * 32, c0 = blockIdx.x * 32;
    int tx = threadIdx.x, ty = threadIdx.y;
#pragma unroll
    for (int i = 0; i < 4; i++) {
        long o = ibo + (long)(r0 + ty + i * 8) * ldin + c0 + tx;
        th[ty + i * 8][tx] = ih[o];
        tl[ty + i * 8][tx] = il[o];
    }
    __syncthreads();
    long ob = (long)blockIdx.z * sOut;
#pragma unroll
    for (int i = 0; i < 4; i++) {
        long o = ob + (long)(c0 + ty + i * 8) * R + r0 + tx;
        oh[o] = th[tx][ty + i * 8];
        ol[o] = tl[tx][ty + i * 8];
    }
}

// ---------------------------------------------------------------------------
extern "C" void kernel_launch(void* const* d_in, const int* in_sizes, int n_in,
                              void* d_out, int out_size)
{
    const float* y  = (const float*)d_in[0];
    const float* Wk = (const float*)d_in[1];
    const float* Wq = (const float*)d_in[2];
    const float* Wv = (const float*)d_in[3];
    const float* Wo = (const float*)d_in[4];

    float* out = (float*)d_out;
    float* Aw  = out + (long)BB * NN * DD;

    __nv_bfloat16 *yh, *yl, *Wh, *Wl, *Ph, *Pl, *VTh, *VTl, *ATh, *ATl, *mh, *ml;
    float* inv;
    cudaGetSymbolAddress((void**)&yh, g_yh);   cudaGetSymbolAddress((void**)&yl, g_yl);
    cudaGetSymbolAddress((void**)&Wh, g_Wh);   cudaGetSymbolAddress((void**)&Wl, g_Wl);
    cudaGetSymbolAddress((void**)&Ph, g_Ph);   cudaGetSymbolAddress((void**)&Pl, g_Pl);
    cudaGetSymbolAddress((void**)&VTh, g_VTh); cudaGetSymbolAddress((void**)&VTl, g_VTl);
    cudaGetSymbolAddress((void**)&ATh, g_ATh); cudaGetSymbolAddress((void**)&ATl, g_ATl);
    cudaGetSymbolAddress((void**)&mh, g_mh);   cudaGetSymbolAddress((void**)&ml, g_ml);
    cudaGetSymbolAddress((void**)&inv, g_inv);

    cudaFuncSetAttribute(gemm_hmma, cudaFuncAttributeMaxDynamicSharedMemorySize, SMEMB);

    const long nd = (long)NN * DD;
    const long np = (long)NN * PP;
    const long nn = (long)NN * NN;
    const long dd = (long)DD * DD;
    const long nY = (long)BB * NN * DD;

    // 1) splits: W stacked [Wk; 0.1*Wq; Wv; Wo] (one launch), then y
    {
        dim3 gw((unsigned)(dd / 1024), 1, 4);
        splitW_k<<<gw, 256>>>(Wk, Wq, Wv, Wo, Wh, Wl);
        splitf_k<<<(int)(nY / 1024), 256>>>(y, yh, yl, nY);
    }

    // 2) fused projection: P[8192, 6144] = y @ [Wk;0.1Wq;Wv]^T -> bf16 split
    {
        dim3 g(PP / 128, (BB * NN) / 128, 1);
        gemm_hmma<<<g, 256, SMEMB>>>(yh, yl, Wh, Wl, nullptr, Ph, Pl,
                                     PP, DD, DD, DD, 0, 0, 0, 1.0f, 1);
    }

    // 3) V transpose (independent of logits; bf16 hi/lo direct)
    {
        dim3 g2(DD / 32, NN / 32, BB);
        tbf16_k<<<g2, dim3(32, 8)>>>(Ph + 2 * DD, Pl + 2 * DD, VTh, VTl,
                                     NN, DD, PP, np, nd);
    }

    // 4) logits per batch with fused exp: Aw[b] = exp(Q_b @ K_b^T) (fp32)
    {
        dim3 g(NN / 128, NN / 128, BB);
        gemm_hmma<<<g, 256, SMEMB>>>(Ph + DD, Pl + DD, Ph, Pl, Aw, nullptr, nullptr,
                                     NN, DD, PP, PP, np, np, nn, 1.0f, 2);
    }

    // 5) column sums (diag excluded) -> inv
    {
        dim3 g(NN / 256, BB, 1);
        colsum_k<<<g, 256>>>(Aw, inv);
    }

    // 6) fused normalize (writeback, diag=0) + transpose + bf16 split -> AT
    {
        dim3 g(NN / 32, NN / 32, BB);
        normtsplit_k<<<g, dim3(32, 8)>>>(Aw, inv, ATh, ATl);
    }

    // 7) mid[b] = AT_b @ VT_b^T -> bf16 split
    {
        dim3 g(DD / 128, NN / 128, BB);
        gemm_hmma<<<g, 256, SMEMB>>>(ATh, ATl, VTh, VTl, nullptr, mh, ml,
                                     DD, NN, NN, NN, nn, nd, nd, 1.0f, 1);
    }

    // 8) out = mid @ Wo^T (flat) -> fp32 d_out
    {
        dim3 g(DD / 128, (BB * NN) / 128, 1);
        gemm_hmma<<<g, 256, SMEMB>>>(mh, ml, Wh + 3 * dd, Wl + 3 * dd, out, nullptr, nullptr,
                                     DD, DD, DD, DD, 0, 0, 0, 1.0f, 0);
    }
}

// round 6
// speedup vs baseline: 3.3979x; 1.1163x over previous
#include <cuda_runtime.h>
#include <cuda_bf16.h>
#include <cstdint>
#include <cfloat>
#include <math.h>

#define BB 8
#define NN 1024
#define DD 2048
#define PP (3 * DD)   // packed projection width (K|Q|V)

// ---------------------------------------------------------------------------
// Scratch (allocation-free rule: static __device__ arrays)
// ---------------------------------------------------------------------------
static __device__ __align__(16) __nv_bfloat16 g_yh[BB * NN * DD], g_yl[BB * NN * DD];
static __device__ __align__(16) __nv_bfloat16 g_Wh[4 * DD * DD], g_Wl[4 * DD * DD]; // k,q,v,o stacked
static __device__ __align__(16) __nv_bfloat16 g_Ph[BB * NN * PP], g_Pl[BB * NN * PP]; // K|Q|V packed
static __device__ __align__(16) __nv_bfloat16 g_VTh[BB * NN * DD], g_VTl[BB * NN * DD];
static __device__ __align__(16) __nv_bfloat16 g_ATh[BB * NN * NN], g_ATl[BB * NN * NN];
static __device__ __align__(16) __nv_bfloat16 g_mh[BB * NN * DD], g_ml[BB * NN * DD];
static __device__ __align__(16) float         g_inv[BB * NN];

// ---------------------------------------------------------------------------
// Baseline-PTX helpers (sm_103 non-'a': mma.sync / ldmatrix / cp.async)
// ---------------------------------------------------------------------------
__device__ __forceinline__ uint32_t smem_u32(const void* p) {
    uint32_t a;
    asm("{ .reg .u64 t; cvta.to.shared.u64 t, %1; cvt.u32.u64 %0, t; }" : "=r"(a) : "l"(p));
    return a;
}
__device__ __forceinline__ void cp16(uint32_t dst, const void* src) {
    asm volatile("cp.async.cg.shared.global [%0], [%1], 16;" :: "r"(dst), "l"(src) : "memory");
}
#define CP_COMMIT() asm volatile("cp.async.commit_group;" ::: "memory")
#define CP_WAIT1()  asm volatile("cp.async.wait_group 1;" ::: "memory")

__device__ __forceinline__ void ldm_x4(uint32_t& r0, uint32_t& r1, uint32_t& r2, uint32_t& r3,
                                       uint32_t addr) {
    asm volatile("ldmatrix.sync.aligned.m8n8.x4.shared.b16 {%0,%1,%2,%3}, [%4];"
                 : "=r"(r0), "=r"(r1), "=r"(r2), "=r"(r3) : "r"(addr));
}
__device__ __forceinline__ void mma_bf16(float* c, const uint32_t* a, const uint32_t* b) {
    asm volatile(
        "mma.sync.aligned.m16n8k16.row.col.f32.bf16.bf16.f32 "
        "{%0,%1,%2,%3}, {%4,%5,%6,%7}, {%8,%9}, {%0,%1,%2,%3};"
        : "+f"(c[0]), "+f"(c[1]), "+f"(c[2]), "+f"(c[3])
        : "r"(a[0]), "r"(a[1]), "r"(a[2]), "r"(a[3]), "r"(b[0]), "r"(b[1]));
}

// ---------------------------------------------------------------------------
// HMMA GEMM:  C[M,Nc] = alpha * A[M,K] * B[Nc,K]^T   (bf16 hi/lo, fp32 acc)
// tile 128x128x32, 256 threads (8 warps, 64x32 each).
// 3-stage cp.async pipeline, ONE __syncthreads per stage.
// SMEM: XOR-swizzled 64B rows (chunk' = q ^ ((r>>1)&3)) -> conflict-free
// for cp.async stores and all ldmatrix phases; 32KB/stage; 2 CTAs/SM.
// mode 0: fp32 C.  mode 1: bf16 hi/lo split C.  mode 2: fp32 exp(C).
// ---------------------------------------------------------------------------
#define MATB   8192               // 128 rows x 64 B
#define STAGEB (4 * MATB)         // Ah, Al, Bh, Bl = 32768 B
#define NSTG   3
#define SMEMB  (NSTG * STAGEB)    // 98304 B

__global__ __launch_bounds__(256, 2) void gemm_hmma(
    const __nv_bfloat16* __restrict__ Ah, const __nv_bfloat16* __restrict__ Al,
    const __nv_bfloat16* __restrict__ Bh, const __nv_bfloat16* __restrict__ Bl,
    float* __restrict__ Cf, __nv_bfloat16* __restrict__ Ch, __nv_bfloat16* __restrict__ Cl,
    int Nc, int K, int lda, int ldb, long sA, long sB, long sC, float alpha, int mode)
{
    extern __shared__ char smem[];
    const uint32_t sb = smem_u32(smem);

    const int tid  = threadIdx.x;
    const int wid  = tid >> 5;
    const int lane = tid & 31;
    const int m0 = blockIdx.y * 128, n0 = blockIdx.x * 128;

    const __nv_bfloat16* pA[2] = { Ah + (long)blockIdx.z * sA + (long)m0 * lda,
                                   Al + (long)blockIdx.z * sA + (long)m0 * lda };
    const __nv_bfloat16* pB[2] = { Bh + (long)blockIdx.z * sB + (long)n0 * ldb,
                                   Bl + (long)blockIdx.z * sB + (long)n0 * ldb };
    const long zC = (long)blockIdx.z * sC;

    // cp.async indices: 512 chunks (128 rows x 4x16B) per matrix, 2 per thread
    const int r0c = tid >> 2, q0 = tid & 3;
    const int r1c = r0c + 64, q1 = q0;
    const int d0 = r0c * 64 + ((q0 ^ ((r0c >> 1) & 3)) * 16);
    const int d1 = r1c * 64 + ((q1 ^ ((r1c >> 1) & 3)) * 16);

    const int wm0 = (wid >> 2) * 64;
    const int wn0 = (wid & 3) * 32;

    // ldmatrix lane addressing (logical row, chunk within 32B slab)
    const int ra = wm0 + (lane & 15);                      // + 16*mi
    const int qa = (lane >> 4);                            // 0/1
    const int rb = wn0 + ((lane >> 3) & 2) * 4 + (lane & 7); // + 16*nb
    const int qb = ((lane >> 3) & 1);                      // 0/1
    const int sa = (ra >> 1) & 3;   // swizzle sel, invariant under +16*mi
    const int sbw = (rb >> 1) & 3;  // swizzle sel, invariant under +16*nb

    float acc[4][4][4];
#pragma unroll
    for (int i = 0; i < 4; i++)
#pragma unroll
        for (int j = 0; j < 4; j++)
#pragma unroll
            for (int k = 0; k < 4; k++) acc[i][j][k] = 0.f;

    const int nst = K >> 5;

    // ---- prologue: issue stages 0 and 1 ----
#pragma unroll
    for (int pc = 0; pc < 2; pc++) {
        const int k0 = pc << 5;
        uint32_t s0 = sb + pc * STAGEB;
#pragma unroll
        for (int m = 0; m < 2; m++) {
            cp16(s0 + m * MATB + d0, pA[m] + (long)r0c * lda + k0 + q0 * 8);
            cp16(s0 + m * MATB + d1, pA[m] + (long)r1c * lda + k0 + q1 * 8);
            cp16(s0 + (2 + m) * MATB + d0, pB[m] + (long)r0c * ldb + k0 + q0 * 8);
            cp16(s0 + (2 + m) * MATB + d1, pB[m] + (long)r1c * ldb + k0 + q1 * 8);
        }
        CP_COMMIT();
    }

    int slot = 0, nslot = 2;
    for (int c = 0; c < nst; c++) {
        CP_WAIT1();          // stage c resident (c+1 may remain in flight)
        __syncthreads();     // everyone past reading the slot we overwrite next

        if (c + 2 < nst) {
            const int k0 = (c + 2) << 5;
            uint32_t s1 = sb + nslot * STAGEB;
#pragma unroll
            for (int m = 0; m < 2; m++) {
                cp16(s1 + m * MATB + d0, pA[m] + (long)r0c * lda + k0 + q0 * 8);
                cp16(s1 + m * MATB + d1, pA[m] + (long)r1c * lda + k0 + q1 * 8);
                cp16(s1 + (2 + m) * MATB + d0, pB[m] + (long)r0c * ldb + k0 + q0 * 8);
                cp16(s1 + (2 + m) * MATB + d1, pB[m] + (long)r1c * ldb + k0 + q1 * 8);
            }
        }
        CP_COMMIT();
        if (++nslot == NSTG) nslot = 0;

        const uint32_t st = sb + slot * STAGEB;
        if (++slot == NSTG) slot = 0;

#pragma unroll
        for (int s = 0; s < 2; s++) {      // two 16-wide k slabs
            const int qla = (s * 2 + qa) ^ sa;
            const int qlb = (s * 2 + qb) ^ sbw;
            const uint32_t aHb = st + 0 * MATB + ra * 64 + qla * 16;
            const uint32_t aLb = st + 1 * MATB + ra * 64 + qla * 16;
            const uint32_t bHb = st + 2 * MATB + rb * 64 + qlb * 16;
            const uint32_t bLb = st + 3 * MATB + rb * 64 + qlb * 16;

            uint32_t bh[2][4], bl[2][4];
#pragma unroll
            for (int nb = 0; nb < 2; nb++) {
                ldm_x4(bh[nb][0], bh[nb][1], bh[nb][2], bh[nb][3], bHb + nb * 1024);
                ldm_x4(bl[nb][0], bl[nb][1], bl[nb][2], bl[nb][3], bLb + nb * 1024);
            }
#pragma unroll
            for (int mi = 0; mi < 4; mi++) {
                uint32_t ah[4], al[4];
                ldm_x4(ah[0], ah[1], ah[2], ah[3], aHb + mi * 1024);
                ldm_x4(al[0], al[1], al[2], al[3], aLb + mi * 1024);
#pragma unroll
                for (int ni = 0; ni < 4; ni++) {
                    const uint32_t* bhf = &bh[ni >> 1][(ni & 1) * 2];
                    const uint32_t* blf = &bl[ni >> 1][(ni & 1) * 2];
                    mma_bf16(acc[mi][ni], ah, bhf);
                    mma_bf16(acc[mi][ni], ah, blf);
                    mma_bf16(acc[mi][ni], al, bhf);
                }
            }
        }
    }

    // ---- epilogue ----
    const int er = lane >> 2;
    const int ec = (lane & 3) * 2;
#pragma unroll
    for (int mi = 0; mi < 4; mi++) {
#pragma unroll
        for (int ni = 0; ni < 4; ni++) {
            const int row = m0 + wm0 + 16 * mi + er;
            const int col = n0 + wn0 + 8 * ni + ec;
            float v0 = acc[mi][ni][0] * alpha, v1 = acc[mi][ni][1] * alpha;
            float v2 = acc[mi][ni][2] * alpha, v3 = acc[mi][ni][3] * alpha;
            if (mode == 0) {
                *reinterpret_cast<float2*>(Cf + zC + (long)row * Nc + col) = make_float2(v0, v1);
                *reinterpret_cast<float2*>(Cf + zC + (long)(row + 8) * Nc + col) = make_float2(v2, v3);
            } else if (mode == 2) {
                *reinterpret_cast<float2*>(Cf + zC + (long)row * Nc + col) =
                    make_float2(__expf(v0), __expf(v1));
                *reinterpret_cast<float2*>(Cf + zC + (long)(row + 8) * Nc + col) =
                    make_float2(__expf(v2), __expf(v3));
            } else {
                __nv_bfloat162 h, l;
                h.x = __float2bfloat16(v0); l.x = __float2bfloat16(v0 - __bfloat162float(h.x));
                h.y = __float2bfloat16(v1); l.y = __float2bfloat16(v1 - __bfloat162float(h.y));
                *reinterpret_cast<__nv_bfloat162*>(Ch + zC + (long)row * Nc + col) = h;
                *reinterpret_cast<__nv_bfloat162*>(Cl + zC + (long)row * Nc + col) = l;
                h.x = __float2bfloat16(v2); l.x = __float2bfloat16(v2 - __bfloat162float(h.x));
                h.y = __float2bfloat16(v3); l.y = __float2bfloat16(v3 - __bfloat162float(h.y));
                *reinterpret_cast<__nv_bfloat162*>(Ch + zC + (long)(row + 8) * Nc + col) = h;
                *reinterpret_cast<__nv_bfloat162*>(Cl + zC + (long)(row + 8) * Nc + col) = l;
            }
        }
    }
}

// ---------------------------------------------------------------------------
// fp32 -> bf16 hi/lo elementwise split (y)
// ---------------------------------------------------------------------------
__global__ __launch_bounds__(256) void splitf_k(const float* __restrict__ x,
    __nv_bfloat16* __restrict__ hi, __nv_bfloat16* __restrict__ lo, long n)
{
    long i = ((long)blockIdx.x * 256 + threadIdx.x) * 4;
    if (i >= n) return;
    float4 v = *reinterpret_cast<const float4*>(x + i);
    __nv_bfloat162 h01, h23, l01, l23;
    h01.x = __float2bfloat16(v.x); l01.x = __float2bfloat16(v.x - __bfloat162float(h01.x));
    h01.y = __float2bfloat16(v.y); l01.y = __float2bfloat16(v.y - __bfloat162float(h01.y));
    h23.x = __float2bfloat16(v.z); l23.x = __float2bfloat16(v.z - __bfloat162float(h23.x));
    h23.y = __float2bfloat16(v.w); l23.y = __float2bfloat16(v.w - __bfloat162float(h23.y));
    uint2 hv, lv;
    hv.x = *reinterpret_cast<uint32_t*>(&h01); hv.y = *reinterpret_cast<uint32_t*>(&h23);
    lv.x = *reinterpret_cast<uint32_t*>(&l01); lv.y = *reinterpret_cast<uint32_t*>(&l23);
    *reinterpret_cast<uint2*>(hi + i) = hv;
    *reinterpret_cast<uint2*>(lo + i) = lv;
}

// ---------------------------------------------------------------------------
// 4 weight matrices split in one launch (z selects source; Wq scaled by 0.1)
// ---------------------------------------------------------------------------
__global__ __launch_bounds__(256) void splitW_k(
    const float* __restrict__ w0, const float* __restrict__ w1,
    const float* __restrict__ w2, const float* __restrict__ w3,
    __nv_bfloat16* __restrict__ hi, __nv_bfloat16* __restrict__ lo)
{
    const int z = blockIdx.z;
    const float* src = (z == 0) ? w0 : (z == 1) ? w1 : (z == 2) ? w2 : w3;
    const float scale = (z == 1) ? 0.1f : 1.0f;
    const long dd = (long)DD * DD;
    long i = ((long)blockIdx.x * 256 + threadIdx.x) * 4;
    if (i >= dd) return;
    float4 v = *reinterpret_cast<const float4*>(src + i);
    v.x *= scale; v.y *= scale; v.z *= scale; v.w *= scale;
    __nv_bfloat162 h01, h23, l01, l23;
    h01.x = __float2bfloat16(v.x); l01.x = __float2bfloat16(v.x - __bfloat162float(h01.x));
    h01.y = __float2bfloat16(v.y); l01.y = __float2bfloat16(v.y - __bfloat162float(h01.y));
    h23.x = __float2bfloat16(v.z); l23.x = __float2bfloat16(v.z - __bfloat162float(h23.x));
    h23.y = __float2bfloat16(v.w); l23.y = __float2bfloat16(v.w - __bfloat162float(h23.y));
    long o = z * dd + i;
    uint2 hv, lv;
    hv.x = *reinterpret_cast<uint32_t*>(&h01); hv.y = *reinterpret_cast<uint32_t*>(&h23);
    lv.x = *reinterpret_cast<uint32_t*>(&l01); lv.y = *reinterpret_cast<uint32_t*>(&l23);
    *reinterpret_cast<uint2*>(hi + o) = hv;
    *reinterpret_cast<uint2*>(lo + o) = lv;
}

// ---------------------------------------------------------------------------
// Column sums of exp-logits (diag excluded) -> inv[b][j] = 1/sum
// ---------------------------------------------------------------------------
__global__ __launch_bounds__(256) void colsum_k(const float* __restrict__ Aw,
                                                float* __restrict__ inv)
{
    const int j = blockIdx.x * blockDim.x + threadIdx.x;
    const float* Mb = Aw + (long)blockIdx.y * NN * NN;
    float s0 = 0.f, s1 = 0.f, s2 = 0.f, s3 = 0.f;
#pragma unroll 4
    for (int i = 0; i < NN; i += 4) {
        s0 += Mb[(long)(i + 0) * NN + j];
        s1 += Mb[(long)(i + 1) * NN + j];
        s2 += Mb[(long)(i + 2) * NN + j];
        s3 += Mb[(long)(i + 3) * NN + j];
    }
    float s = (s0 + s1) + (s2 + s3);
    s -= Mb[(long)j * NN + j];   // exclude diagonal junk term
    inv[blockIdx.y * NN + j] = 1.f / s;
}

// ---------------------------------------------------------------------------
// Fused: normalize exp-Aw (write back fp32, diag=0) + transpose + bf16 split.
// AT[j][i] = Aw[i][j] * inv[j]  (diag 0)
// ---------------------------------------------------------------------------
__global__ __launch_bounds__(256) void normtsplit_k(float* __restrict__ Aw,
    const float* __restrict__ inv,
    __nv_bfloat16* __restrict__ oh, __nv_bfloat16* __restrict__ ol)
{
    __shared__ float t[32][33];
    const long nn = (long)NN * NN;
    float* Mb = Aw + (long)blockIdx.z * nn;
    const float* ib = inv + (long)blockIdx.z * NN;
    int r0 = blockIdx.y * 32, c0 = blockIdx.x * 32;
    int tx = threadIdx.x, ty = threadIdx.y;
    const float sc = ib[c0 + tx];           // normalization for column c0+tx
#pragma unroll
    for (int i = 0; i < 4; i++) {
        int r = r0 + ty + i * 8;
        long o = (long)r * NN + c0 + tx;
        float v = Mb[o] * sc;
        if (r == c0 + tx) v = 0.f;
        Mb[o] = v;                          // write back normalized weights
        t[ty + i * 8][tx] = v;
    }
    __syncthreads();
    long ob = (long)blockIdx.z * nn;
#pragma unroll
    for (int i = 0; i < 4; i++) {
        float v = t[tx][ty + i * 8];
        __nv_bfloat16 h = __float2bfloat16(v);
        __nv_bfloat16 l = __float2bfloat16(v - __bfloat162float(h));
        long o = ob + (long)(c0 + ty + i * 8) * NN + r0 + tx;
        oh[o] = h; ol[o] = l;
    }
}

// ---------------------------------------------------------------------------
// bf16 transpose (hi & lo in one pass): out[c][r] = in[r][c]
// ---------------------------------------------------------------------------
__global__ __launch_bounds__(256) void tbf16_k(
    const __nv_bfloat16* __restrict__ ih, const __nv_bfloat16* __restrict__ il,
    __nv_bfloat16* __restrict__ oh, __nv_bfloat16* __restrict__ ol,
    int R, int C, int ldin, long sIn, long sOut)
{
    __shared__ __nv_bfloat16 th[32][33], tl[32][33];
    long ibo = (long)blockIdx.z * sIn;
    int r0 = blockIdx.y * 32, c0 = blockIdx.x * 32;
    int tx = threadIdx.x, ty = threadIdx.y;
#pragma unroll
    for (int i = 0; i < 4; i++) {
        long o = ibo + (long)(r0 + ty + i * 8) * ldin + c0 + tx;
        th[ty + i * 8][tx] = ih[o];
        tl[ty + i * 8][tx] = il[o];
    }
    __syncthreads();
    long ob = (long)blockIdx.z * sOut;
#pragma unroll
    for (int i = 0; i < 4; i++) {
        long o = ob + (long)(c0 + ty + i * 8) * R + r0 + tx;
        oh[o] = th[tx][ty + i * 8];
        ol[o] = tl[tx][ty + i * 8];
    }
}

// ---------------------------------------------------------------------------
extern "C" void kernel_launch(void* const* d_in, const int* in_sizes, int n_in,
                              void* d_out, int out_size)
{
    const float* y  = (const float*)d_in[0];
    const float* Wk = (const float*)d_in[1];
    const float* Wq = (const float*)d_in[2];
    const float* Wv = (const float*)d_in[3];
    const float* Wo = (const float*)d_in[4];

    float* out = (float*)d_out;
    float* Aw  = out + (long)BB * NN * DD;

    __nv_bfloat16 *yh, *yl, *Wh, *Wl, *Ph, *Pl, *VTh, *VTl, *ATh, *ATl, *mh, *ml;
    float* inv;
    cudaGetSymbolAddress((void**)&yh, g_yh);   cudaGetSymbolAddress((void**)&yl, g_yl);
    cudaGetSymbolAddress((void**)&Wh, g_Wh);   cudaGetSymbolAddress((void**)&Wl, g_Wl);
    cudaGetSymbolAddress((void**)&Ph, g_Ph);   cudaGetSymbolAddress((void**)&Pl, g_Pl);
    cudaGetSymbolAddress((void**)&VTh, g_VTh); cudaGetSymbolAddress((void**)&VTl, g_VTl);
    cudaGetSymbolAddress((void**)&ATh, g_ATh); cudaGetSymbolAddress((void**)&ATl, g_ATl);
    cudaGetSymbolAddress((void**)&mh, g_mh);   cudaGetSymbolAddress((void**)&ml, g_ml);
    cudaGetSymbolAddress((void**)&inv, g_inv);

    cudaFuncSetAttribute(gemm_hmma, cudaFuncAttributeMaxDynamicSharedMemorySize, SMEMB);

    const long nd = (long)NN * DD;
    const long np = (long)NN * PP;
    const long nn = (long)NN * NN;
    const long dd = (long)DD * DD;
    const long nY = (long)BB * NN * DD;

    // 1) splits: W stacked [Wk; 0.1*Wq; Wv; Wo] (one launch), then y
    {
        dim3 gw((unsigned)(dd / 1024), 1, 4);
        splitW_k<<<gw, 256>>>(Wk, Wq, Wv, Wo, Wh, Wl);
        splitf_k<<<(int)(nY / 1024), 256>>>(y, yh, yl, nY);
    }

    // 2) fused projection: P[8192, 6144] = y @ [Wk;0.1Wq;Wv]^T -> bf16 split
    {
        dim3 g(PP / 128, (BB * NN) / 128, 1);
        gemm_hmma<<<g, 256, SMEMB>>>(yh, yl, Wh, Wl, nullptr, Ph, Pl,
                                     PP, DD, DD, DD, 0, 0, 0, 1.0f, 1);
    }

    // 3) logits per batch with fused exp: Aw[b] = exp(Q_b @ K_b^T) (fp32)
    //    (placed early so ncu's fixed capture slot lands on this GEMM)
    {
        dim3 g(NN / 128, NN / 128, BB);
        gemm_hmma<<<g, 256, SMEMB>>>(Ph + DD, Pl + DD, Ph, Pl, Aw, nullptr, nullptr,
                                     NN, DD, PP, PP, np, np, nn, 1.0f, 2);
    }

    // 4) V transpose (bf16 hi/lo direct)
    {
        dim3 g2(DD / 32, NN / 32, BB);
        tbf16_k<<<g2, dim3(32, 8)>>>(Ph + 2 * DD, Pl + 2 * DD, VTh, VTl,
                                     NN, DD, PP, np, nd);
    }

    // 5) column sums (diag excluded) -> inv
    {
        dim3 g(NN / 256, BB, 1);
        colsum_k<<<g, 256>>>(Aw, inv);
    }

    // 6) fused normalize (writeback, diag=0) + transpose + bf16 split -> AT
    {
        dim3 g(NN / 32, NN / 32, BB);
        normtsplit_k<<<g, dim3(32, 8)>>>(Aw, inv, ATh, ATl);
    }

    // 7) mid[b] = AT_b @ VT_b^T -> bf16 split
    {
        dim3 g(DD / 128, NN / 128, BB);
        gemm_hmma<<<g, 256, SMEMB>>>(ATh, ATl, VTh, VTl, nullptr, mh, ml,
                                     DD, NN, NN, NN, nn, nd, nd, 1.0f, 1);
    }

    // 8) out = mid @ Wo^T (flat) -> fp32 d_out
    {
        dim3 g(DD / 128, (BB * NN) / 128, 1);
        gemm_hmma<<<g, 256, SMEMB>>>(mh, ml, Wh + 3 * dd, Wl + 3 * dd, out, nullptr, nullptr,
                                     DD, DD, DD, DD, 0, 0, 0, 1.0f, 0);
    }
}